// round 2
// baseline (speedup 1.0000x reference)
#include <cuda_runtime.h>
#include <cuda_bf16.h>

#define H 64

static const int MAXN = 100352;   // N = 100000 in dataset, padded
static const int MAXE = 1605632;  // E = 1600000 in dataset, padded

// ---- device scratch (allocation-free contract: __device__ globals) ----
__device__ __align__(16) float g_h[(size_t)MAXN * H];    // h = feat@W + b
__device__ __align__(16) float g_agg[(size_t)MAXN * H];  // segment_sum(v * h[col]) by row
__device__ float g_ssrc[MAXN];
__device__ float g_sdst[MAXN];
__device__ float g_z[MAXN];
__device__ unsigned int g_smax[MAXN];
__device__ float g_scores[MAXE];

// monotonic unsigned encoding of float for atomicMax (0u encodes "-inf")
__device__ __forceinline__ unsigned fenc(float f) {
    unsigned u = __float_as_uint(f);
    return (u & 0x80000000u) ? ~u : (u | 0x80000000u);
}
__device__ __forceinline__ float fdec(unsigned u) {
    return (u & 0x80000000u) ? __uint_as_float(u ^ 0x80000000u)
                             : __uint_as_float(~u);
}

// ---------------------------------------------------------------- init
__global__ void init_kernel(int N) {
    int stride = gridDim.x * blockDim.x;
    int i = blockIdx.x * blockDim.x + threadIdx.x;
    int total = N * H;
    for (int j = i; j < total; j += stride) g_agg[j] = 0.0f;
    for (int j = i; j < N; j += stride) {
        g_z[j] = 0.0f;
        g_smax[j] = 0u;
    }
}

// ---------------------------------------------------------------- GEMM
// h[N,64] = feat[N,F] @ W[F,64] + b[64]; BM=64, BN=64, BK=32, 256 threads,
// 4x4 microtile per thread. sA stored transposed [k][m].
__global__ void gemm_kernel(const float* __restrict__ feat,
                            const float* __restrict__ W,
                            const float* __restrict__ bias,
                            int N, int F) {
    __shared__ float sA[32][64];
    __shared__ float sB[32][64];
    int tid = threadIdx.x;
    int tx = tid & 15, ty = tid >> 4;
    int rowBase = blockIdx.x * 64;

    float acc[4][4];
#pragma unroll
    for (int i = 0; i < 4; i++)
#pragma unroll
        for (int j = 0; j < 4; j++) acc[i][j] = 0.0f;

    int ar = tid >> 2;            // 0..63 (row within tile)
    int ak = (tid & 3) * 8;       // k offset: 0,8,16,24
    int br = tid >> 3;            // 0..31 (k row of W tile)
    int bc = (tid & 7) * 8;       // col offset: 0..56

    for (int kb = 0; kb < F; kb += 32) {
        float4 a0 = make_float4(0.f, 0.f, 0.f, 0.f), a1 = a0;
        int grow = rowBase + ar;
        if (grow < N) {
            const float4* ap =
                (const float4*)(feat + (size_t)grow * F + kb + ak);
            a0 = ap[0];
            a1 = ap[1];
        }
        sA[ak + 0][ar] = a0.x; sA[ak + 1][ar] = a0.y;
        sA[ak + 2][ar] = a0.z; sA[ak + 3][ar] = a0.w;
        sA[ak + 4][ar] = a1.x; sA[ak + 5][ar] = a1.y;
        sA[ak + 6][ar] = a1.z; sA[ak + 7][ar] = a1.w;

        const float4* bp = (const float4*)(W + (size_t)(kb + br) * H + bc);
        float4 b0 = bp[0], b1 = bp[1];
        *(float4*)&sB[br][bc] = b0;
        *(float4*)&sB[br][bc + 4] = b1;
        __syncthreads();

#pragma unroll
        for (int k = 0; k < 32; k++) {
            float a[4], b[4];
#pragma unroll
            for (int i = 0; i < 4; i++) a[i] = sA[k][ty * 4 + i];
#pragma unroll
            for (int j = 0; j < 4; j++) b[j] = sB[k][tx * 4 + j];
#pragma unroll
            for (int i = 0; i < 4; i++)
#pragma unroll
                for (int j = 0; j < 4; j++)
                    acc[i][j] = fmaf(a[i], b[j], acc[i][j]);
        }
        __syncthreads();
    }

#pragma unroll
    for (int i = 0; i < 4; i++) {
        int row = rowBase + ty * 4 + i;
        if (row < N) {
            float4 o;
            o.x = acc[i][0] + bias[tx * 4 + 0];
            o.y = acc[i][1] + bias[tx * 4 + 1];
            o.z = acc[i][2] + bias[tx * 4 + 2];
            o.w = acc[i][3] + bias[tx * 4 + 3];
            *(float4*)&g_h[(size_t)row * H + tx * 4] = o;
        }
    }
}

// ------------------------------------------------------- edge aggregation
// 16 threads per edge; each thread one float4 of the H=64 feature vector.
// agg[row] += v * h[col] via red.global.add.v4.f32 (sm_90+).
__global__ void agg_kernel(const int* __restrict__ row_idx,
                           const int* __restrict__ col_idx,
                           const float* __restrict__ vv, int E) {
    long long t = (long long)blockIdx.x * blockDim.x + threadIdx.x;
    long long e = t >> 4;
    if (e >= E) return;
    int s = (int)(threadIdx.x & 15);
    int row = row_idx[e];
    int col = col_idx[e];
    float v = vv[e];
    float4 hv = *(const float4*)(g_h + (size_t)col * H + s * 4);
    float* p = g_agg + (size_t)row * H + s * 4;
    asm volatile("red.global.add.v4.f32 [%0], {%1, %2, %3, %4};" ::"l"(p),
                 "f"(v * hv.x), "f"(v * hv.y), "f"(v * hv.z), "f"(v * hv.w)
                 : "memory");
}

// ------------------------------------------------- per-node score vectors
// emb = relu(agg); s_src = emb . w[0:64]; s_dst = emb . w[64:128]
// one warp per node, 2 features per lane.
__global__ void svec_kernel(const float* __restrict__ wmlp, int N) {
    int warp = (blockIdx.x * blockDim.x + threadIdx.x) >> 5;
    int lane = threadIdx.x & 31;
    if (warp >= N) return;
    float e0 = fmaxf(g_agg[(size_t)warp * H + lane], 0.0f);
    float e1 = fmaxf(g_agg[(size_t)warp * H + 32 + lane], 0.0f);
    float ps = e0 * wmlp[lane] + e1 * wmlp[lane + 32];
    float pd = e0 * wmlp[64 + lane] + e1 * wmlp[96 + lane];
#pragma unroll
    for (int o = 16; o; o >>= 1) {
        ps += __shfl_down_sync(0xFFFFFFFFu, ps, o);
        pd += __shfl_down_sync(0xFFFFFFFFu, pd, o);
    }
    if (lane == 0) {
        g_ssrc[warp] = ps;
        g_sdst[warp] = pd;
    }
}

// ------------------------------------------------- scores + segment max
// (b_mlp cancels exactly in the softmax, so it is omitted)
__global__ void score_kernel(const int* __restrict__ row_idx,
                             const int* __restrict__ col_idx, int E) {
    int e = blockIdx.x * blockDim.x + threadIdx.x;
    if (e >= E) return;
    int row = row_idx[e];
    int col = col_idx[e];
    float sc = g_ssrc[row] + g_sdst[col];
    g_scores[e] = sc;
    atomicMax(&g_smax[row], fenc(sc));
}

// ------------------------------------------------- exp + segment sum
__global__ void expz_kernel(const int* __restrict__ row_idx, int E) {
    int e = blockIdx.x * blockDim.x + threadIdx.x;
    if (e >= E) return;
    int row = row_idx[e];
    float m = fdec(g_smax[row]);
    float ex = __expf(g_scores[e] - m);
    g_scores[e] = ex;
    atomicAdd(&g_z[row], ex);
}

// ------------------------------------------------- final edge values
__global__ void final_kernel(const int* __restrict__ row_idx,
                             const float* __restrict__ vv,
                             float* __restrict__ out, int E) {
    int e = blockIdx.x * blockDim.x + threadIdx.x;
    if (e >= E) return;
    int row = row_idx[e];
    out[e] = vv[e] + g_scores[e] / g_z[row];
}

// ---------------------------------------------------------------- launch
extern "C" void kernel_launch(void* const* d_in, const int* in_sizes, int n_in,
                              void* d_out, int out_size) {
    const float* feat = (const float*)d_in[0];
    const float* vv = (const float*)d_in[1];
    const float* W = (const float*)d_in[2];
    const float* bg = (const float*)d_in[3];
    const float* wm = (const float*)d_in[4];
    // d_in[5] = b_mlp: cancels in softmax (and is zero); unused.
    const int* vidx = (const int*)d_in[6];   // int32 (JAX x64 disabled)

    int F = in_sizes[2] / H;       // 256
    int N = in_sizes[0] / F;       // 100000
    int E = in_sizes[1];           // 1600000
    const int* row_idx = vidx;
    const int* col_idx = vidx + E;
    float* out = (float*)d_out;

    init_kernel<<<2048, 256>>>(N);
    gemm_kernel<<<(N + 63) / 64, 256>>>(feat, W, bg, N, F);
    {
        long long threads = (long long)E * 16;
        int blocks = (int)((threads + 255) / 256);
        agg_kernel<<<blocks, 256>>>(row_idx, col_idx, vv, E);
    }
    svec_kernel<<<(N + 7) / 8, 256>>>(wm, N);
    int eb = (E + 255) / 256;
    score_kernel<<<eb, 256>>>(row_idx, col_idx, E);
    expz_kernel<<<eb, 256>>>(row_idx, E);
    final_kernel<<<eb, 256>>>(row_idx, vv, out, E);
}

// round 3
// speedup vs baseline: 1.1306x; 1.1306x over previous
#include <cuda_runtime.h>
#include <cuda_bf16.h>

#define H 64

static const int MAXN = 100352;   // N = 100000 in dataset, padded
static const int MAXE = 1605632;  // E = 1600000 in dataset, padded
static const int SCAN_BLK = 1024;
static const int MAX_BLKS = (MAXN + SCAN_BLK - 1) / SCAN_BLK;

// ---- device scratch (allocation-free contract: __device__ globals) ----
__device__ __align__(16) float g_h[(size_t)MAXN * H];  // h = feat@W + b
__device__ float g_sdst[MAXN];                         // relu(agg) . w2
__device__ int g_cnt[MAXN];                            // per-row edge count
__device__ int g_part[MAXN];                           // scan partials
__device__ int g_bsum[MAX_BLKS + 1];                   // scan block sums
__device__ int g_start[MAXN + 1];                      // CSR row starts
__device__ int g_cur[MAXN];                            // scatter cursors
__device__ int g_ecol[MAXE];                           // CSR col
__device__ float g_eval[MAXE];                         // CSR v
__device__ int g_eid[MAXE];                            // CSR original edge id

__device__ __forceinline__ float neg_inf() {
    return __int_as_float(0xff800000);
}

// ---------------------------------------------------------------- init
__global__ void init_kernel(int N) {
    int i = blockIdx.x * blockDim.x + threadIdx.x;
    int stride = gridDim.x * blockDim.x;
    for (int j = i; j < N; j += stride) g_cnt[j] = 0;
}

// ---------------------------------------------------------------- GEMM
// h[N,64] = feat[N,F] @ W[F,64] + b[64]; BM=64, BN=64, BK=32, 256 threads,
// 4x4 microtile per thread. sA stored transposed [k][m].
__global__ void gemm_kernel(const float* __restrict__ feat,
                            const float* __restrict__ W,
                            const float* __restrict__ bias,
                            int N, int F) {
    __shared__ float sA[32][64];
    __shared__ float sB[32][64];
    int tid = threadIdx.x;
    int tx = tid & 15, ty = tid >> 4;
    int rowBase = blockIdx.x * 64;

    float acc[4][4];
#pragma unroll
    for (int i = 0; i < 4; i++)
#pragma unroll
        for (int j = 0; j < 4; j++) acc[i][j] = 0.0f;

    int ar = tid >> 2;
    int ak = (tid & 3) * 8;
    int br = tid >> 3;
    int bc = (tid & 7) * 8;

    for (int kb = 0; kb < F; kb += 32) {
        float4 a0 = make_float4(0.f, 0.f, 0.f, 0.f), a1 = a0;
        int grow = rowBase + ar;
        if (grow < N) {
            const float4* ap =
                (const float4*)(feat + (size_t)grow * F + kb + ak);
            a0 = ap[0];
            a1 = ap[1];
        }
        sA[ak + 0][ar] = a0.x; sA[ak + 1][ar] = a0.y;
        sA[ak + 2][ar] = a0.z; sA[ak + 3][ar] = a0.w;
        sA[ak + 4][ar] = a1.x; sA[ak + 5][ar] = a1.y;
        sA[ak + 6][ar] = a1.z; sA[ak + 7][ar] = a1.w;

        const float4* bp = (const float4*)(W + (size_t)(kb + br) * H + bc);
        float4 b0 = bp[0], b1 = bp[1];
        *(float4*)&sB[br][bc] = b0;
        *(float4*)&sB[br][bc + 4] = b1;
        __syncthreads();

#pragma unroll
        for (int k = 0; k < 32; k++) {
            float a[4], b[4];
#pragma unroll
            for (int i = 0; i < 4; i++) a[i] = sA[k][ty * 4 + i];
#pragma unroll
            for (int j = 0; j < 4; j++) b[j] = sB[k][tx * 4 + j];
#pragma unroll
            for (int i = 0; i < 4; i++)
#pragma unroll
                for (int j = 0; j < 4; j++)
                    acc[i][j] = fmaf(a[i], b[j], acc[i][j]);
        }
        __syncthreads();
    }

#pragma unroll
    for (int i = 0; i < 4; i++) {
        int row = rowBase + ty * 4 + i;
        if (row < N) {
            float4 o;
            o.x = acc[i][0] + bias[tx * 4 + 0];
            o.y = acc[i][1] + bias[tx * 4 + 1];
            o.z = acc[i][2] + bias[tx * 4 + 2];
            o.w = acc[i][3] + bias[tx * 4 + 3];
            *(float4*)&g_h[(size_t)row * H + tx * 4] = o;
        }
    }
}

// ------------------------------------------------------------- CSR build
__global__ void hist_kernel(const int* __restrict__ row_idx, int E) {
    int i = blockIdx.x * blockDim.x + threadIdx.x;
    int stride = gridDim.x * blockDim.x;
    for (int e = i; e < E; e += stride) atomicAdd(&g_cnt[row_idx[e]], 1);
}

// inclusive scan within 1024-element blocks
__global__ void scan1_kernel(int N) {
    __shared__ int sh[SCAN_BLK];
    int tid = threadIdx.x;
    int i = blockIdx.x * SCAN_BLK + tid;
    int c = (i < N) ? g_cnt[i] : 0;
    sh[tid] = c;
    __syncthreads();
#pragma unroll
    for (int off = 1; off < SCAN_BLK; off <<= 1) {
        int t = (tid >= off) ? sh[tid - off] : 0;
        __syncthreads();
        sh[tid] += t;
        __syncthreads();
    }
    if (i < N) g_part[i] = sh[tid];
    if (tid == SCAN_BLK - 1) g_bsum[blockIdx.x] = sh[tid];
}

// serial exclusive scan of block sums (tiny: ~98 entries)
__global__ void scan2_kernel(int nb) {
    if (threadIdx.x == 0 && blockIdx.x == 0) {
        int run = 0;
        for (int b = 0; b < nb; b++) {
            int t = g_bsum[b];
            g_bsum[b] = run;
            run += t;
        }
    }
}

__global__ void scan3_kernel(int N, int E) {
    int i = blockIdx.x * blockDim.x + threadIdx.x;
    if (i >= N) return;
    int excl = g_bsum[i >> 10] + g_part[i] - g_cnt[i];
    g_start[i] = excl;
    g_cur[i] = excl;
    if (i == N - 1) g_start[N] = E;
}

__global__ void scatter_kernel(const int* __restrict__ row_idx,
                               const int* __restrict__ col_idx,
                               const float* __restrict__ vv, int E) {
    int i = blockIdx.x * blockDim.x + threadIdx.x;
    int stride = gridDim.x * blockDim.x;
    for (int e = i; e < E; e += stride) {
        int r = row_idx[e];
        int p = atomicAdd(&g_cur[r], 1);
        g_ecol[p] = col_idx[e];
        g_eval[p] = vv[e];
        g_eid[p] = e;
    }
}

// -------------------------------------------------- fused agg + sdst
// One warp per row. Lanes split into two halves; each half handles one edge
// at a time, 16 lanes x float4 = 64 features. Accumulate in registers,
// combine halves, relu, dot with w2, store scalar sdst. g_agg never exists.
__global__ void agg_sdst_kernel(const float* __restrict__ wmlp, int N) {
    int w = (blockIdx.x * blockDim.x + threadIdx.x) >> 5;
    if (w >= N) return;
    int lane = threadIdx.x & 31;
    int half = lane >> 4;
    int seg = lane & 15;

    int s = g_start[w];
    int eend = g_start[w + 1];

    float4 acc = make_float4(0.f, 0.f, 0.f, 0.f);
    for (int p = s + half; p < eend; p += 2) {
        int col = g_ecol[p];
        float v = g_eval[p];
        float4 hv = *(const float4*)(g_h + (size_t)col * H + seg * 4);
        acc.x = fmaf(v, hv.x, acc.x);
        acc.y = fmaf(v, hv.y, acc.y);
        acc.z = fmaf(v, hv.z, acc.z);
        acc.w = fmaf(v, hv.w, acc.w);
    }
    // combine the two halves (lane l += lane l+16)
    acc.x += __shfl_down_sync(0xFFFFFFFFu, acc.x, 16);
    acc.y += __shfl_down_sync(0xFFFFFFFFu, acc.y, 16);
    acc.z += __shfl_down_sync(0xFFFFFFFFu, acc.z, 16);
    acc.w += __shfl_down_sync(0xFFFFFFFFu, acc.w, 16);

    float pd = 0.0f;
    if (half == 0) {
        float4 w2 = *(const float4*)(wmlp + H + seg * 4);
        pd = fmaxf(acc.x, 0.f) * w2.x + fmaxf(acc.y, 0.f) * w2.y +
             fmaxf(acc.z, 0.f) * w2.z + fmaxf(acc.w, 0.f) * w2.w;
    }
#pragma unroll
    for (int o = 8; o; o >>= 1) pd += __shfl_down_sync(0xFFFFFFFFu, pd, o);
    if (lane == 0) g_sdst[w] = pd;
}

// -------------------------------------------- fused softmax + output
// One warp per row, atomic-free. s_src[row] cancels in the row-segment
// softmax, so scores reduce to sdst[col]. Computes segment max, Z, and
// writes out[eid] = v + exp(sdst[col]-m)/Z in one kernel.
__global__ void softmax_out_kernel(float* __restrict__ out, int N) {
    int w = (blockIdx.x * blockDim.x + threadIdx.x) >> 5;
    if (w >= N) return;
    int lane = threadIdx.x & 31;
    int s = g_start[w];
    int eend = g_start[w + 1];
    int n = eend - s;
    if (n == 0) return;

    if (n <= 32) {
        int p = s + lane;
        bool act = p < eend;
        float sc = neg_inf();
        if (act) sc = g_sdst[g_ecol[p]];
        float m = sc;
#pragma unroll
        for (int o = 16; o; o >>= 1)
            m = fmaxf(m, __shfl_xor_sync(0xFFFFFFFFu, m, o));
        float ex = act ? __expf(sc - m) : 0.0f;
        float z = ex;
#pragma unroll
        for (int o = 16; o; o >>= 1) z += __shfl_xor_sync(0xFFFFFFFFu, z, o);
        if (act) out[g_eid[p]] = g_eval[p] + ex / z;
    } else {
        float m = neg_inf();
        for (int p = s + lane; p < eend; p += 32)
            m = fmaxf(m, g_sdst[g_ecol[p]]);
#pragma unroll
        for (int o = 16; o; o >>= 1)
            m = fmaxf(m, __shfl_xor_sync(0xFFFFFFFFu, m, o));
        float z = 0.0f;
        for (int p = s + lane; p < eend; p += 32)
            z += __expf(g_sdst[g_ecol[p]] - m);
#pragma unroll
        for (int o = 16; o; o >>= 1) z += __shfl_xor_sync(0xFFFFFFFFu, z, o);
        float inv_z = 1.0f / z;
        for (int p = s + lane; p < eend; p += 32)
            out[g_eid[p]] = g_eval[p] + __expf(g_sdst[g_ecol[p]] - m) * inv_z;
    }
}

// ---------------------------------------------------------------- launch
extern "C" void kernel_launch(void* const* d_in, const int* in_sizes, int n_in,
                              void* d_out, int out_size) {
    const float* feat = (const float*)d_in[0];
    const float* vv = (const float*)d_in[1];
    const float* W = (const float*)d_in[2];
    const float* bg = (const float*)d_in[3];
    const float* wm = (const float*)d_in[4];
    // d_in[5] = b_mlp: cancels in softmax; unused.
    const int* vidx = (const int*)d_in[6];  // int32 (JAX x64 disabled)

    int F = in_sizes[2] / H;  // 256
    int N = in_sizes[0] / F;  // 100000
    int E = in_sizes[1];      // 1600000
    const int* row_idx = vidx;
    const int* col_idx = vidx + E;
    float* out = (float*)d_out;

    int eb = (E + 255) / 256;
    int nb = (N + 255) / 256;
    int nscan = (N + SCAN_BLK - 1) / SCAN_BLK;
    int wb = (N * 32 + 255) / 256;  // warp-per-row grids

    init_kernel<<<512, 256>>>(N);
    gemm_kernel<<<(N + 63) / 64, 256>>>(feat, W, bg, N, F);
    hist_kernel<<<eb, 256>>>(row_idx, E);
    scan1_kernel<<<nscan, SCAN_BLK>>>(N);
    scan2_kernel<<<1, 32>>>(nscan);
    scan3_kernel<<<nb, 256>>>(N, E);
    scatter_kernel<<<eb, 256>>>(row_idx, col_idx, vv, E);
    agg_sdst_kernel<<<wb, 256>>>(wm, N);
    softmax_out_kernel<<<wb, 256>>>(out, N);
}

// round 4
// speedup vs baseline: 1.4604x; 1.2917x over previous
#include <cuda_runtime.h>
#include <cuda_bf16.h>
#include <stdint.h>

#define H 64

static const int MAXN = 100352;   // N = 100000 in dataset, padded
static const int MAXE = 1605632;  // E = 1600000 in dataset, padded
static const int SCAN_BLK = 1024;
static const int MAX_BLKS = (MAXN + SCAN_BLK - 1) / SCAN_BLK;  // 98 <= 128

// ---- device scratch (allocation-free contract: __device__ globals) ----
__device__ __align__(16) float g_h[(size_t)MAXN * H];  // h = feat@W + b
__device__ float g_sdst[MAXN];                         // relu(agg) . w2
__device__ int g_cnt[MAXN];                            // per-row edge count
__device__ int g_part[MAXN];                           // scan partials
__device__ int g_bsum[MAX_BLKS + 32];                  // scan block sums
__device__ int g_start[MAXN + 1];                      // CSR row starts
__device__ int g_cur[MAXN];                            // scatter cursors
__device__ __align__(16) int4 g_edge[MAXE];            // {col, v_bits, eid, 0}

__device__ __forceinline__ float neg_inf() {
    return __int_as_float(0xff800000);
}
__device__ __forceinline__ uint32_t f2tf32(float f) {
    uint32_t r;
    asm("cvt.rna.tf32.f32 %0, %1;" : "=r"(r) : "f"(f));
    return r;
}
__device__ __forceinline__ void mma_tf32(float c[4], uint32_t a0, uint32_t a1,
                                         uint32_t a2, uint32_t a3, uint32_t b0,
                                         uint32_t b1) {
    asm volatile(
        "mma.sync.aligned.m16n8k8.row.col.f32.tf32.tf32.f32 "
        "{%0,%1,%2,%3}, {%4,%5,%6,%7}, {%8,%9}, {%0,%1,%2,%3};"
        : "+f"(c[0]), "+f"(c[1]), "+f"(c[2]), "+f"(c[3])
        : "r"(a0), "r"(a1), "r"(a2), "r"(a3), "r"(b0), "r"(b1));
}

// ---------------------------------------------------------------- init
__global__ void init_kernel(int N) {
    int i = blockIdx.x * blockDim.x + threadIdx.x;
    int stride = gridDim.x * blockDim.x;
    for (int j = i; j < N; j += stride) g_cnt[j] = 0;
}

// ------------------------------------------------------------ tf32 GEMM
// h[N,64] = feat[N,F] @ W[F,64] + b. Block tile 128x64, 8 warps (4Mx2N),
// warp tile 32x32 = 2x4 m16n8k8 mma. W held entirely in smem (tf32) with
// swizzle addr = (k>>2)*256 + n*4 + (k&3) -> fragment reads lane-linear.
// A chunks 128x32 in smem, swizzle addr = (kc)*516 + m*4 + (k&3) (pad 4).
__global__ void gemm_tf32_kernel(const float* __restrict__ feat,
                                 const float* __restrict__ W,
                                 const float* __restrict__ bias,
                                 int N, int F) {
    extern __shared__ uint32_t smem[];
    uint32_t* sW = smem;            // F*64 entries
    uint32_t* sA = smem + F * H;    // 8 chunks * 516

    int tid = threadIdx.x;
    int lane = tid & 31, wid = tid >> 5;
    int gid = lane >> 2, tig = lane & 3;
    int mbase = (wid >> 1) * 32;
    int nbase = (wid & 1) * 32;
    int rowBase = blockIdx.x * 128;

    // load whole W as tf32 into smem
    int nIterW = (F * H / 4) / 256;  // F/16
    for (int it = 0; it < nIterW; it++) {
        int idx4 = it * 256 + tid;
        int k = idx4 >> 4;
        int n4 = (idx4 & 15) * 4;
        float4 w4 = ((const float4*)W)[idx4];
        uint32_t base = (k >> 2) * 256 + (k & 3);
        sW[base + (n4 + 0) * 4] = f2tf32(w4.x);
        sW[base + (n4 + 1) * 4] = f2tf32(w4.y);
        sW[base + (n4 + 2) * 4] = f2tf32(w4.z);
        sW[base + (n4 + 3) * 4] = f2tf32(w4.w);
    }

    float acc[2][4][4];
#pragma unroll
    for (int mt = 0; mt < 2; mt++)
#pragma unroll
        for (int nt = 0; nt < 4; nt++)
#pragma unroll
            for (int j = 0; j < 4; j++) acc[mt][nt][j] = 0.0f;

    int nkb = F / 32;
    for (int kb = 0; kb < nkb; kb++) {
        __syncthreads();
        // load A chunk: 128 rows x 32 k (8 float4 per row)
#pragma unroll
        for (int i = 0; i < 4; i++) {
            int fid = i * 256 + tid;
            int row = fid >> 3;
            int q = fid & 7;
            int grow = rowBase + row;
            float4 a = make_float4(0.f, 0.f, 0.f, 0.f);
            if (grow < N)
                a = ((const float4*)(feat + (size_t)grow * F + kb * 32))[q];
            uint32_t* dst = sA + q * 516 + row * 4;
            dst[0] = f2tf32(a.x);
            dst[1] = f2tf32(a.y);
            dst[2] = f2tf32(a.z);
            dst[3] = f2tf32(a.w);
        }
        __syncthreads();

#pragma unroll
        for (int ks = 0; ks < 4; ks++) {
            int kc0 = ks * 2, kc1 = kc0 + 1;
            int kg0 = kb * 8 + kc0, kg1 = kg0 + 1;
            uint32_t b0[4], b1[4];
#pragma unroll
            for (int nt = 0; nt < 4; nt++) {
                int c = nbase + nt * 8 + gid;
                b0[nt] = sW[kg0 * 256 + c * 4 + tig];
                b1[nt] = sW[kg1 * 256 + c * 4 + tig];
            }
#pragma unroll
            for (int mt = 0; mt < 2; mt++) {
                int r = mbase + mt * 16 + gid;
                uint32_t a0 = sA[kc0 * 516 + r * 4 + tig];
                uint32_t a1 = sA[kc0 * 516 + (r + 8) * 4 + tig];
                uint32_t a2 = sA[kc1 * 516 + r * 4 + tig];
                uint32_t a3 = sA[kc1 * 516 + (r + 8) * 4 + tig];
#pragma unroll
                for (int nt = 0; nt < 4; nt++)
                    mma_tf32(acc[mt][nt], a0, a1, a2, a3, b0[nt], b1[nt]);
            }
        }
    }

    // epilogue: add bias, store float2 pairs
#pragma unroll
    for (int mt = 0; mt < 2; mt++) {
        int r0 = rowBase + mbase + mt * 16 + gid;
        int r1 = r0 + 8;
#pragma unroll
        for (int nt = 0; nt < 4; nt++) {
            int c = nbase + nt * 8 + 2 * tig;
            float bx = __ldg(bias + c), by = __ldg(bias + c + 1);
            if (r0 < N) {
                float2 o = make_float2(acc[mt][nt][0] + bx,
                                       acc[mt][nt][1] + by);
                *(float2*)&g_h[(size_t)r0 * H + c] = o;
            }
            if (r1 < N) {
                float2 o = make_float2(acc[mt][nt][2] + bx,
                                       acc[mt][nt][3] + by);
                *(float2*)&g_h[(size_t)r1 * H + c] = o;
            }
        }
    }
}

// ------------------------------------------------------------- CSR build
__global__ void hist_kernel(const int* __restrict__ row_idx, int E) {
    int i = blockIdx.x * blockDim.x + threadIdx.x;
    int stride = gridDim.x * blockDim.x;
    for (int e = i; e < E; e += stride) atomicAdd(&g_cnt[row_idx[e]], 1);
}

// inclusive scan within 1024-element blocks
__global__ void scan1_kernel(int N) {
    __shared__ int sh[SCAN_BLK];
    int tid = threadIdx.x;
    int i = blockIdx.x * SCAN_BLK + tid;
    int c = (i < N) ? g_cnt[i] : 0;
    sh[tid] = c;
    __syncthreads();
#pragma unroll
    for (int off = 1; off < SCAN_BLK; off <<= 1) {
        int t = (tid >= off) ? sh[tid - off] : 0;
        __syncthreads();
        sh[tid] += t;
        __syncthreads();
    }
    if (i < N) g_part[i] = sh[tid];
    if (tid == SCAN_BLK - 1) g_bsum[blockIdx.x] = sh[tid];
}

// parallel exclusive scan of block sums (nb <= 128)
__global__ void scan2_kernel(int nb) {
    __shared__ int sh[128];
    int t = threadIdx.x;
    int v = (t < nb) ? g_bsum[t] : 0;
    sh[t] = v;
    __syncthreads();
#pragma unroll
    for (int off = 1; off < 128; off <<= 1) {
        int u = (t >= off) ? sh[t - off] : 0;
        __syncthreads();
        sh[t] += u;
        __syncthreads();
    }
    if (t < nb) g_bsum[t] = sh[t] - v;  // exclusive
}

__global__ void scan3_kernel(int N, int E) {
    int i = blockIdx.x * blockDim.x + threadIdx.x;
    if (i >= N) return;
    int excl = g_bsum[i >> 10] + g_part[i] - g_cnt[i];
    g_start[i] = excl;
    g_cur[i] = excl;
    if (i == N - 1) g_start[N] = E;
}

__global__ void scatter_kernel(const int* __restrict__ row_idx,
                               const int* __restrict__ col_idx,
                               const float* __restrict__ vv, int E) {
    int i = blockIdx.x * blockDim.x + threadIdx.x;
    int stride = gridDim.x * blockDim.x;
    for (int e = i; e < E; e += stride) {
        int r = row_idx[e];
        int p = atomicAdd(&g_cur[r], 1);
        g_edge[p] = make_int4(col_idx[e], __float_as_int(vv[e]), e, 0);
    }
}

// -------------------------------------------------- fused agg + sdst
// One warp per row; two half-warps each handle one edge at a time,
// 16 lanes x float4 = 64 features. Register accumulate, relu, dot w2.
__global__ void agg_sdst_kernel(const float* __restrict__ wmlp, int N) {
    int w = (blockIdx.x * blockDim.x + threadIdx.x) >> 5;
    if (w >= N) return;
    int lane = threadIdx.x & 31;
    int half = lane >> 4;
    int seg = lane & 15;

    int s = g_start[w];
    int eend = g_start[w + 1];

    float4 acc = make_float4(0.f, 0.f, 0.f, 0.f);
    for (int p = s + half; p < eend; p += 2) {
        int4 ed = g_edge[p];  // broadcast within half-warp
        float v = __int_as_float(ed.y);
        float4 hv = *(const float4*)(g_h + (size_t)ed.x * H + seg * 4);
        acc.x = fmaf(v, hv.x, acc.x);
        acc.y = fmaf(v, hv.y, acc.y);
        acc.z = fmaf(v, hv.z, acc.z);
        acc.w = fmaf(v, hv.w, acc.w);
    }
    acc.x += __shfl_down_sync(0xFFFFFFFFu, acc.x, 16);
    acc.y += __shfl_down_sync(0xFFFFFFFFu, acc.y, 16);
    acc.z += __shfl_down_sync(0xFFFFFFFFu, acc.z, 16);
    acc.w += __shfl_down_sync(0xFFFFFFFFu, acc.w, 16);

    float pd = 0.0f;
    if (half == 0) {
        float4 w2 = *(const float4*)(wmlp + H + seg * 4);
        pd = fmaxf(acc.x, 0.f) * w2.x + fmaxf(acc.y, 0.f) * w2.y +
             fmaxf(acc.z, 0.f) * w2.z + fmaxf(acc.w, 0.f) * w2.w;
    }
#pragma unroll
    for (int o = 8; o; o >>= 1) pd += __shfl_down_sync(0xFFFFFFFFu, pd, o);
    if (lane == 0) g_sdst[w] = pd;
}

// -------------------------------------------- fused softmax + output
// s_src[row] cancels in the row-segment softmax -> scores = sdst[col].
__global__ void softmax_out_kernel(float* __restrict__ out, int N) {
    int w = (blockIdx.x * blockDim.x + threadIdx.x) >> 5;
    if (w >= N) return;
    int lane = threadIdx.x & 31;
    int s = g_start[w];
    int eend = g_start[w + 1];
    int n = eend - s;
    if (n == 0) return;

    if (n <= 32) {
        int p = s + lane;
        bool act = p < eend;
        int4 ed = act ? g_edge[p] : make_int4(0, 0, 0, 0);
        float sc = act ? g_sdst[ed.x] : neg_inf();
        float m = sc;
#pragma unroll
        for (int o = 16; o; o >>= 1)
            m = fmaxf(m, __shfl_xor_sync(0xFFFFFFFFu, m, o));
        float ex = act ? __expf(sc - m) : 0.0f;
        float z = ex;
#pragma unroll
        for (int o = 16; o; o >>= 1) z += __shfl_xor_sync(0xFFFFFFFFu, z, o);
        if (act) out[ed.z] = __int_as_float(ed.y) + ex / z;
    } else {
        float m = neg_inf();
        for (int p = s + lane; p < eend; p += 32)
            m = fmaxf(m, g_sdst[g_edge[p].x]);
#pragma unroll
        for (int o = 16; o; o >>= 1)
            m = fmaxf(m, __shfl_xor_sync(0xFFFFFFFFu, m, o));
        float z = 0.0f;
        for (int p = s + lane; p < eend; p += 32)
            z += __expf(g_sdst[g_edge[p].x] - m);
#pragma unroll
        for (int o = 16; o; o >>= 1) z += __shfl_xor_sync(0xFFFFFFFFu, z, o);
        float inv_z = 1.0f / z;
        for (int p = s + lane; p < eend; p += 32) {
            int4 ed = g_edge[p];
            out[ed.z] =
                __int_as_float(ed.y) + __expf(g_sdst[ed.x] - m) * inv_z;
        }
    }
}

// ---------------------------------------------------------------- launch
extern "C" void kernel_launch(void* const* d_in, const int* in_sizes, int n_in,
                              void* d_out, int out_size) {
    const float* feat = (const float*)d_in[0];
    const float* vv = (const float*)d_in[1];
    const float* W = (const float*)d_in[2];
    const float* bg = (const float*)d_in[3];
    const float* wm = (const float*)d_in[4];
    // d_in[5] = b_mlp: cancels in softmax; unused.
    const int* vidx = (const int*)d_in[6];  // int32 (JAX x64 disabled)

    int F = in_sizes[2] / H;  // 256
    int N = in_sizes[0] / F;  // 100000
    int E = in_sizes[1];      // 1600000
    const int* row_idx = vidx;
    const int* col_idx = vidx + E;
    float* out = (float*)d_out;

    int eb = (E + 255) / 256;
    int nb = (N + 255) / 256;
    int nscan = (N + SCAN_BLK - 1) / SCAN_BLK;
    int wb = (N * 32 + 255) / 256;  // warp-per-row grids

    size_t gemm_smem = (size_t)(F * H + 8 * 516) * 4;  // tf32 W + A chunk
    cudaFuncSetAttribute(gemm_tf32_kernel,
                         cudaFuncAttributeMaxDynamicSharedMemorySize,
                         (int)gemm_smem);

    init_kernel<<<512, 256>>>(N);
    gemm_tf32_kernel<<<(N + 127) / 128, 256, gemm_smem>>>(feat, W, bg, N, F);
    hist_kernel<<<eb, 256>>>(row_idx, E);
    scan1_kernel<<<nscan, SCAN_BLK>>>(N);
    scan2_kernel<<<1, 128>>>(nscan);
    scan3_kernel<<<nb, 256>>>(N, E);
    scatter_kernel<<<eb, 256>>>(row_idx, col_idx, vv, E);
    agg_sdst_kernel<<<wb, 256>>>(wm, N);
    softmax_out_kernel<<<wb, 256>>>(out, N);
}

// round 5
// speedup vs baseline: 1.4770x; 1.0114x over previous
#include <cuda_runtime.h>
#include <cuda_bf16.h>
#include <cuda_fp16.h>
#include <stdint.h>

#define H 64

static const int MAXN = 100352;   // N = 100000 in dataset, padded
static const int MAXE = 1605632;  // E = 1600000 in dataset, padded
static const int SCAN_BLK = 1024;
static const int MAX_BLKS = (MAXN + SCAN_BLK - 1) / SCAN_BLK;  // 98 <= 128

// ---- device scratch (allocation-free contract: __device__ globals) ----
__device__ __align__(16) __half g_hh[(size_t)MAXN * H];  // h in fp16
__device__ float g_sdst[MAXN];                           // relu(agg) . w2
__device__ int g_cnt[MAXN];                              // per-row edge count
__device__ int g_part[MAXN];                             // scan partials
__device__ int g_bsum[MAX_BLKS + 32];                    // scan block sums
__device__ int g_start[MAXN + 1];                        // CSR row starts
__device__ int g_cur[MAXN];                              // scatter cursors
__device__ __align__(16) int4 g_edge[MAXE];              // {col, v_bits, eid, 0}

__device__ __forceinline__ float neg_inf() {
    return __int_as_float(0xff800000);
}
__device__ __forceinline__ uint32_t f2tf32(float f) {
    uint32_t r;
    asm("cvt.rna.tf32.f32 %0, %1;" : "=r"(r) : "f"(f));
    return r;
}
__device__ __forceinline__ void mma_tf32(float c[4], uint32_t a0, uint32_t a1,
                                         uint32_t a2, uint32_t a3, uint32_t b0,
                                         uint32_t b1) {
    asm volatile(
        "mma.sync.aligned.m16n8k8.row.col.f32.tf32.tf32.f32 "
        "{%0,%1,%2,%3}, {%4,%5,%6,%7}, {%8,%9}, {%0,%1,%2,%3};"
        : "+f"(c[0]), "+f"(c[1]), "+f"(c[2]), "+f"(c[3])
        : "r"(a0), "r"(a1), "r"(a2), "r"(a3), "r"(b0), "r"(b1));
}

// ---------------------------------------------------------------- init
__global__ void init_kernel(int N) {
    int i = blockIdx.x * blockDim.x + threadIdx.x;
    int stride = gridDim.x * blockDim.x;
    for (int j = i; j < N; j += stride) g_cnt[j] = 0;
}

// ------------------------------------------------------------ tf32 GEMM
// h[N,64] = feat[N,F] @ W[F,64] + b, output stored fp16 (only the agg
// gather consumes h). Block tile 128x64, 8 warps (4Mx2N), warp tile
// 32x32 = 2x4 m16n8k8 mma. W whole in smem (tf32), swizzle
// (k>>2)*256 + n*4 + (k&3); A chunks 128x32, (kc)*516 + m*4 + (k&3).
__global__ void gemm_tf32_kernel(const float* __restrict__ feat,
                                 const float* __restrict__ W,
                                 const float* __restrict__ bias,
                                 int N, int F) {
    extern __shared__ uint32_t smem[];
    uint32_t* sW = smem;          // F*64 entries
    uint32_t* sA = smem + F * H;  // 8 chunks * 516

    int tid = threadIdx.x;
    int lane = tid & 31, wid = tid >> 5;
    int gid = lane >> 2, tig = lane & 3;
    int mbase = (wid >> 1) * 32;
    int nbase = (wid & 1) * 32;
    int rowBase = blockIdx.x * 128;

    int nIterW = (F * H / 4) / 256;  // F/16
    for (int it = 0; it < nIterW; it++) {
        int idx4 = it * 256 + tid;
        int k = idx4 >> 4;
        int n4 = (idx4 & 15) * 4;
        float4 w4 = ((const float4*)W)[idx4];
        uint32_t base = (k >> 2) * 256 + (k & 3);
        sW[base + (n4 + 0) * 4] = f2tf32(w4.x);
        sW[base + (n4 + 1) * 4] = f2tf32(w4.y);
        sW[base + (n4 + 2) * 4] = f2tf32(w4.z);
        sW[base + (n4 + 3) * 4] = f2tf32(w4.w);
    }

    float acc[2][4][4];
#pragma unroll
    for (int mt = 0; mt < 2; mt++)
#pragma unroll
        for (int nt = 0; nt < 4; nt++)
#pragma unroll
            for (int j = 0; j < 4; j++) acc[mt][nt][j] = 0.0f;

    int nkb = F / 32;
    for (int kb = 0; kb < nkb; kb++) {
        __syncthreads();
#pragma unroll
        for (int i = 0; i < 4; i++) {
            int fid = i * 256 + tid;
            int row = fid >> 3;
            int q = fid & 7;
            int grow = rowBase + row;
            float4 a = make_float4(0.f, 0.f, 0.f, 0.f);
            if (grow < N)
                a = ((const float4*)(feat + (size_t)grow * F + kb * 32))[q];
            uint32_t* dst = sA + q * 516 + row * 4;
            dst[0] = f2tf32(a.x);
            dst[1] = f2tf32(a.y);
            dst[2] = f2tf32(a.z);
            dst[3] = f2tf32(a.w);
        }
        __syncthreads();

#pragma unroll
        for (int ks = 0; ks < 4; ks++) {
            int kc0 = ks * 2, kc1 = kc0 + 1;
            int kg0 = kb * 8 + kc0, kg1 = kg0 + 1;
            uint32_t b0[4], b1[4];
#pragma unroll
            for (int nt = 0; nt < 4; nt++) {
                int c = nbase + nt * 8 + gid;
                b0[nt] = sW[kg0 * 256 + c * 4 + tig];
                b1[nt] = sW[kg1 * 256 + c * 4 + tig];
            }
#pragma unroll
            for (int mt = 0; mt < 2; mt++) {
                int r = mbase + mt * 16 + gid;
                uint32_t a0 = sA[kc0 * 516 + r * 4 + tig];
                uint32_t a1 = sA[kc0 * 516 + (r + 8) * 4 + tig];
                uint32_t a2 = sA[kc1 * 516 + r * 4 + tig];
                uint32_t a3 = sA[kc1 * 516 + (r + 8) * 4 + tig];
#pragma unroll
                for (int nt = 0; nt < 4; nt++)
                    mma_tf32(acc[mt][nt], a0, a1, a2, a3, b0[nt], b1[nt]);
            }
        }
    }

    // epilogue: add bias, convert to fp16, store half2 pairs
#pragma unroll
    for (int mt = 0; mt < 2; mt++) {
        int r0 = rowBase + mbase + mt * 16 + gid;
        int r1 = r0 + 8;
#pragma unroll
        for (int nt = 0; nt < 4; nt++) {
            int c = nbase + nt * 8 + 2 * tig;
            float bx = __ldg(bias + c), by = __ldg(bias + c + 1);
            if (r0 < N)
                *(__half2*)&g_hh[(size_t)r0 * H + c] =
                    __floats2half2_rn(acc[mt][nt][0] + bx,
                                      acc[mt][nt][1] + by);
            if (r1 < N)
                *(__half2*)&g_hh[(size_t)r1 * H + c] =
                    __floats2half2_rn(acc[mt][nt][2] + bx,
                                      acc[mt][nt][3] + by);
        }
    }
}

// ------------------------------------------------------------- CSR build
__global__ void hist_kernel(const int* __restrict__ row_idx, int E) {
    int i = blockIdx.x * blockDim.x + threadIdx.x;
    int stride = gridDim.x * blockDim.x;
    int E4 = E >> 2;
    const int4* r4 = (const int4*)row_idx;
    for (int e = i; e < E4; e += stride) {
        int4 r = r4[e];
        atomicAdd(&g_cnt[r.x], 1);
        atomicAdd(&g_cnt[r.y], 1);
        atomicAdd(&g_cnt[r.z], 1);
        atomicAdd(&g_cnt[r.w], 1);
    }
    for (int e = E4 * 4 + i; e < E; e += stride) atomicAdd(&g_cnt[row_idx[e]], 1);
}

// shuffle-based inclusive scan within 1024-element blocks
__global__ void scan1_kernel(int N) {
    __shared__ int wsum[32];
    int tid = threadIdx.x;
    int lane = tid & 31, wid = tid >> 5;
    int i = blockIdx.x * SCAN_BLK + tid;
    int x = (i < N) ? g_cnt[i] : 0;
#pragma unroll
    for (int off = 1; off < 32; off <<= 1) {
        int t = __shfl_up_sync(0xFFFFFFFFu, x, off);
        if (lane >= off) x += t;
    }
    if (lane == 31) wsum[wid] = x;
    __syncthreads();
    if (wid == 0) {
        int s = wsum[lane];
#pragma unroll
        for (int off = 1; off < 32; off <<= 1) {
            int t = __shfl_up_sync(0xFFFFFFFFu, s, off);
            if (lane >= off) s += t;
        }
        wsum[lane] = s;
    }
    __syncthreads();
    if (wid > 0) x += wsum[wid - 1];
    if (i < N) g_part[i] = x;
    if (tid == SCAN_BLK - 1) g_bsum[blockIdx.x] = x;
}

// parallel exclusive scan of block sums (nb <= 128)
__global__ void scan2_kernel(int nb) {
    __shared__ int sh[128];
    int t = threadIdx.x;
    int v = (t < nb) ? g_bsum[t] : 0;
    sh[t] = v;
    __syncthreads();
#pragma unroll
    for (int off = 1; off < 128; off <<= 1) {
        int u = (t >= off) ? sh[t - off] : 0;
        __syncthreads();
        sh[t] += u;
        __syncthreads();
    }
    if (t < nb) g_bsum[t] = sh[t] - v;  // exclusive
}

__global__ void scan3_kernel(int N, int E) {
    int i = blockIdx.x * blockDim.x + threadIdx.x;
    if (i >= N) return;
    int excl = g_bsum[i >> 10] + g_part[i] - g_cnt[i];
    g_start[i] = excl;
    g_cur[i] = excl;
    if (i == N - 1) g_start[N] = E;
}

__global__ void scatter_kernel(const int* __restrict__ row_idx,
                               const int* __restrict__ col_idx,
                               const float* __restrict__ vv, int E) {
    int i = blockIdx.x * blockDim.x + threadIdx.x;
    int stride = gridDim.x * blockDim.x;
    int E4 = E >> 2;
    const int4* r4 = (const int4*)row_idx;
    const int4* c4 = (const int4*)col_idx;
    const float4* v4 = (const float4*)vv;
    for (int e = i; e < E4; e += stride) {
        int4 r = r4[e];
        int4 c = c4[e];
        float4 v = v4[e];
        int base = e * 4;
        int p0 = atomicAdd(&g_cur[r.x], 1);
        g_edge[p0] = make_int4(c.x, __float_as_int(v.x), base + 0, 0);
        int p1 = atomicAdd(&g_cur[r.y], 1);
        g_edge[p1] = make_int4(c.y, __float_as_int(v.y), base + 1, 0);
        int p2 = atomicAdd(&g_cur[r.z], 1);
        g_edge[p2] = make_int4(c.z, __float_as_int(v.z), base + 2, 0);
        int p3 = atomicAdd(&g_cur[r.w], 1);
        g_edge[p3] = make_int4(c.w, __float_as_int(v.w), base + 3, 0);
    }
    for (int e = E4 * 4 + i; e < E; e += stride) {
        int p = atomicAdd(&g_cur[row_idx[e]], 1);
        g_edge[p] = make_int4(col_idx[e], __float_as_int(vv[e]), e, 0);
    }
}

// -------------------------------------------------- fused agg + sdst
// One warp per row; two half-warps each handle one edge at a time,
// 16 lanes x 4 fp16 features (8B load) = 64. fp32 accumulate, relu, dot w2.
__global__ void agg_sdst_kernel(const float* __restrict__ wmlp, int N) {
    int w = (blockIdx.x * blockDim.x + threadIdx.x) >> 5;
    if (w >= N) return;
    int lane = threadIdx.x & 31;
    int half = lane >> 4;
    int seg = lane & 15;

    int s = g_start[w];
    int eend = g_start[w + 1];

    float4 acc = make_float4(0.f, 0.f, 0.f, 0.f);
    for (int p = s + half; p < eend; p += 2) {
        int4 ed = g_edge[p];  // broadcast within half-warp
        float v = __int_as_float(ed.y);
        uint2 u = *(const uint2*)(g_hh + (size_t)ed.x * H + seg * 4);
        float2 f01 = __half22float2(*(const __half2*)&u.x);
        float2 f23 = __half22float2(*(const __half2*)&u.y);
        acc.x = fmaf(v, f01.x, acc.x);
        acc.y = fmaf(v, f01.y, acc.y);
        acc.z = fmaf(v, f23.x, acc.z);
        acc.w = fmaf(v, f23.y, acc.w);
    }
    acc.x += __shfl_down_sync(0xFFFFFFFFu, acc.x, 16);
    acc.y += __shfl_down_sync(0xFFFFFFFFu, acc.y, 16);
    acc.z += __shfl_down_sync(0xFFFFFFFFu, acc.z, 16);
    acc.w += __shfl_down_sync(0xFFFFFFFFu, acc.w, 16);

    float pd = 0.0f;
    if (half == 0) {
        float4 w2 = *(const float4*)(wmlp + H + seg * 4);
        pd = fmaxf(acc.x, 0.f) * w2.x + fmaxf(acc.y, 0.f) * w2.y +
             fmaxf(acc.z, 0.f) * w2.z + fmaxf(acc.w, 0.f) * w2.w;
    }
#pragma unroll
    for (int o = 8; o; o >>= 1) pd += __shfl_down_sync(0xFFFFFFFFu, pd, o);
    if (lane == 0) g_sdst[w] = pd;
}

// -------------------------------------------- fused softmax + output
// s_src[row] cancels in the row-segment softmax -> scores = sdst[col].
__global__ void softmax_out_kernel(float* __restrict__ out, int N) {
    int w = (blockIdx.x * blockDim.x + threadIdx.x) >> 5;
    if (w >= N) return;
    int lane = threadIdx.x & 31;
    int s = g_start[w];
    int eend = g_start[w + 1];
    int n = eend - s;
    if (n == 0) return;

    if (n <= 32) {
        int p = s + lane;
        bool act = p < eend;
        int4 ed = act ? g_edge[p] : make_int4(0, 0, 0, 0);
        float sc = act ? g_sdst[ed.x] : neg_inf();
        float m = sc;
#pragma unroll
        for (int o = 16; o; o >>= 1)
            m = fmaxf(m, __shfl_xor_sync(0xFFFFFFFFu, m, o));
        float ex = act ? __expf(sc - m) : 0.0f;
        float z = ex;
#pragma unroll
        for (int o = 16; o; o >>= 1) z += __shfl_xor_sync(0xFFFFFFFFu, z, o);
        if (act) out[ed.z] = __int_as_float(ed.y) + ex / z;
    } else {
        float m = neg_inf();
        for (int p = s + lane; p < eend; p += 32)
            m = fmaxf(m, g_sdst[g_edge[p].x]);
#pragma unroll
        for (int o = 16; o; o >>= 1)
            m = fmaxf(m, __shfl_xor_sync(0xFFFFFFFFu, m, o));
        float z = 0.0f;
        for (int p = s + lane; p < eend; p += 32)
            z += __expf(g_sdst[g_edge[p].x] - m);
#pragma unroll
        for (int o = 16; o; o >>= 1) z += __shfl_xor_sync(0xFFFFFFFFu, z, o);
        float inv_z = 1.0f / z;
        for (int p = s + lane; p < eend; p += 32) {
            int4 ed = g_edge[p];
            out[ed.z] =
                __int_as_float(ed.y) + __expf(g_sdst[ed.x] - m) * inv_z;
        }
    }
}

// ---------------------------------------------------------------- launch
extern "C" void kernel_launch(void* const* d_in, const int* in_sizes, int n_in,
                              void* d_out, int out_size) {
    const float* feat = (const float*)d_in[0];
    const float* vv = (const float*)d_in[1];
    const float* W = (const float*)d_in[2];
    const float* bg = (const float*)d_in[3];
    const float* wm = (const float*)d_in[4];
    // d_in[5] = b_mlp: cancels in softmax; unused.
    const int* vidx = (const int*)d_in[6];  // int32 (JAX x64 disabled)

    int F = in_sizes[2] / H;  // 256
    int N = in_sizes[0] / F;  // 100000
    int E = in_sizes[1];      // 1600000
    const int* row_idx = vidx;
    const int* col_idx = vidx + E;
    float* out = (float*)d_out;

    int eb = (E + 255) / 256;
    int nb = (N + 255) / 256;
    int nscan = (N + SCAN_BLK - 1) / SCAN_BLK;
    int wb = (N * 32 + 255) / 256;  // warp-per-row grids

    size_t gemm_smem = (size_t)(F * H + 8 * 516) * 4;  // tf32 W + A chunk
    cudaFuncSetAttribute(gemm_tf32_kernel,
                         cudaFuncAttributeMaxDynamicSharedMemorySize,
                         (int)gemm_smem);

    init_kernel<<<512, 256>>>(N);
    gemm_tf32_kernel<<<(N + 127) / 128, 256, gemm_smem>>>(feat, W, bg, N, F);
    hist_kernel<<<eb / 4 + 1, 256>>>(row_idx, E);
    scan1_kernel<<<nscan, SCAN_BLK>>>(N);
    scan2_kernel<<<1, 128>>>(nscan);
    scan3_kernel<<<nb, 256>>>(N, E);
    scatter_kernel<<<eb / 4 + 1, 256>>>(row_idx, col_idx, vv, E);
    agg_sdst_kernel<<<wb, 256>>>(wm, N);
    softmax_out_kernel<<<wb, 256>>>(out, N);
}